// round 12
// baseline (speedup 1.0000x reference)
#include <cuda_runtime.h>
#include <cstdint>

#define GNUM   2048
#define NPG    57
#define NNODES (GNUM*NPG)      // 116736
#define EPG    160
#define NEDGES (GNUM*EPG)      // 327680
#define HID    256
#define NLAY   5
#define NEF    (GNUM*80)       // 163840
#define NGRID  (NNODES/128)    // 912

// ---------------- scratch ----------------
__device__ float d_h   [(size_t)NNODES*HID];
__device__ float d_t2  [(size_t)NNODES*HID];
__device__ float d_agg [(size_t)NNODES*HID];
__device__ float d_P   [(size_t)NNODES*HID];
__device__ float d_Q   [(size_t)NNODES*HID];
__device__ float d_invdeg [NNODES];
__device__ float d_b2f    [NNODES];
__device__ float d_bnscale[NLAY*HID];
__device__ float d_bnshift[NLAY*HID];
__device__ float d_wcf [(size_t)256*256];
__device__ float d_cvec[(size_t)NLAY*HID];
__device__ float d_zeros[HID];
// int8 activation planes + row scales
__device__ unsigned char d_h8h[(size_t)NNODES*HID];
__device__ unsigned char d_h8l[(size_t)NNODES*HID];
__device__ unsigned char d_a8h[(size_t)NNODES*HID];
__device__ unsigned char d_a8l[(size_t)NNODES*HID];
__device__ unsigned char d_t8h[(size_t)NNODES*HID];
__device__ unsigned char d_t8l[(size_t)NNODES*HID];
__device__ float d_sh[NNODES];
__device__ float d_sa[NNODES];
__device__ float d_st[NNODES];
// int8 weight planes [256 out, K] + per-out scales
__device__ unsigned char d_w8h_m1[(size_t)NLAY*256*512];
__device__ unsigned char d_w8l_m1[(size_t)NLAY*256*512];
__device__ unsigned char d_w8h_u1[(size_t)NLAY*256*512];
__device__ unsigned char d_w8l_u1[(size_t)NLAY*256*512];
__device__ unsigned char d_w8h_u2[(size_t)NLAY*256*256];
__device__ unsigned char d_w8l_u2[(size_t)NLAY*256*256];
__device__ unsigned char d_w8h_c [(size_t)NLAY*256*256];
__device__ unsigned char d_w8l_c [(size_t)NLAY*256*256];
__device__ unsigned char d_w8h_r [(size_t)256*512];
__device__ unsigned char d_w8l_r [(size_t)256*512];
__device__ float d_ws_m1[NLAY*256];
__device__ float d_ws_u1[NLAY*256];
__device__ float d_ws_u2[NLAY*256];
__device__ float d_ws_c [NLAY*256];
__device__ float d_ws_r [256];

// ---------------- PTX helpers ----------------
__device__ __forceinline__ uint32_t smem_u32(const void* p) {
    uint32_t a;
    asm("{ .reg .u64 t; cvta.to.shared.u64 t, %1; cvt.u32.u64 %0, t; }" : "=r"(a) : "l"(p));
    return a;
}
__device__ __forceinline__ void cp_async16(uint32_t smem, const void* g) {
    asm volatile("cp.async.cg.shared.global [%0], [%1], 16;" :: "r"(smem), "l"(g) : "memory");
}
#define CP_COMMIT() asm volatile("cp.async.commit_group;" ::: "memory")
#define CP_WAIT1()  asm volatile("cp.async.wait_group 1;" ::: "memory")
#define CP_WAIT0()  asm volatile("cp.async.wait_group 0;" ::: "memory")

// int8 IMMA: D(s32) += A(s8,m16k32) * B(s8,k32n8)
__device__ __forceinline__ void mma_s8(int* d, const uint32_t* a, const uint32_t* b) {
    asm volatile(
        "mma.sync.aligned.m16n8k32.row.col.s32.s8.s8.s32 "
        "{%0,%1,%2,%3}, {%4,%5,%6,%7}, {%8,%9}, {%0,%1,%2,%3};"
        : "+r"(d[0]), "+r"(d[1]), "+r"(d[2]), "+r"(d[3])
        : "r"(a[0]), "r"(a[1]), "r"(a[2]), "r"(a[3]), "r"(b[0]), "r"(b[1]));
}
__device__ __forceinline__ void red_add_v4(float* p, float a, float b, float c, float d) {
    asm volatile("red.global.add.v4.f32 [%0], {%1, %2, %3, %4};"
                 :: "l"(p), "f"(a), "f"(b), "f"(c), "f"(d) : "memory");
}
// quantize one float to (hi,lo) int8 pair given inv scale
__device__ __forceinline__ void q2(float v, float inv, int& h, int& l) {
    int I = __float2int_rn(v * inv);          // |I| <= 16256
    h = __float2int_rn((float)I * 0.0078125f); // /128, |h| <= 127
    l = I - (h << 7);                          // |l| <= 64
}

// ---------------- helper kernels ----------------
__global__ void zero_agg_kernel() {
    size_t n4 = (size_t)NNODES*HID/4;
    float4 z = make_float4(0.f,0.f,0.f,0.f);
    for (size_t i = (size_t)blockIdx.x*blockDim.x + threadIdx.x; i < n4;
         i += (size_t)gridDim.x*blockDim.x)
        ((float4*)d_agg)[i] = z;
}
__global__ void scale_agg_kernel() {
    size_t n4 = (size_t)NNODES*HID/4;
    for (size_t i = (size_t)blockIdx.x*blockDim.x + threadIdx.x; i < n4;
         i += (size_t)gridDim.x*blockDim.x) {
        int row = (int)(i >> 6);
        float s = d_invdeg[row];
        float4 v = ((float4*)d_agg)[i];
        v.x*=s; v.y*=s; v.z*=s; v.w*=s;
        ((float4*)d_agg)[i] = v;
    }
}
__global__ void deg_zero_kernel() {
    int i = blockIdx.x*blockDim.x + threadIdx.x;
    if (i < NNODES) d_invdeg[i] = 0.f;
}
__global__ void deg_count_kernel(const int* __restrict__ dst) {
    int e = blockIdx.x*blockDim.x + threadIdx.x;
    if (e < NEDGES) atomicAdd(&d_invdeg[dst[e]], 1.f);
}
__global__ void deg_inv_kernel() {
    int i = blockIdx.x*blockDim.x + threadIdx.x;
    if (i < NNODES) {
        float c = d_invdeg[i];
        d_invdeg[i] = 1.f / fmaxf(c, 1.f);
        d_b2f[i] = (c > 0.f) ? 1.f : 0.f;
    }
}
__global__ void bn_prep_kernel(const float* __restrict__ g, const float* __restrict__ b,
                               const float* __restrict__ m, const float* __restrict__ v) {
    int i = blockIdx.x*blockDim.x + threadIdx.x;
    if (i < NLAY*HID) {
        float sc = g[i] * rsqrtf(v[i] + 1e-5f);
        d_bnscale[i] = sc;
        d_bnshift[i] = b[i] - m[i]*sc;
    }
}
__global__ void input_gemm_kernel(const float* __restrict__ x,
                                  const float* __restrict__ w,
                                  const float* __restrict__ b) {
    int n = blockIdx.x;
    int c = threadIdx.x;
    __shared__ float xs[16];
    if (c < 16) xs[c] = x[n*16 + c];
    __syncthreads();
    float acc = b[c];
#pragma unroll
    for (int k = 0; k < 16; k++) acc = fmaf(xs[k], w[k*HID + c], acc);
    d_h[(size_t)n*HID + c] = acc;
}
__global__ void cvec_kernel(const float* __restrict__ b2,
                            const float* __restrict__ u1,
                            float* __restrict__ outc) {
    int n = threadIdx.x;
    float s = 0.f;
    for (int k = 0; k < 256; k++)
        s = fmaf(b2[k], u1[(size_t)(256 + k)*256 + n], s);
    outc[n] = s;
}
// C = msg_w2 @ U1bot, stored [256 k][256 n] fp32
__global__ void cgemm_kernel(const float* __restrict__ w2,
                             const float* __restrict__ u1) {
    int k = blockIdx.x, n = threadIdx.x;
    float s = 0.f;
    for (int j = 0; j < 256; j++)
        s = fmaf(w2[(size_t)k*256 + j], u1[(size_t)(256 + j)*256 + n], s);
    d_wcf[(size_t)k*256 + n] = s;
}
// quantize rows of fp32 [nrows,256] -> hi/lo int8 planes + row scale. warp/row.
__global__ __launch_bounds__(256, 8)
void quant_rows_kernel(const float* __restrict__ src,
                       unsigned char* __restrict__ hi, unsigned char* __restrict__ lo,
                       float* __restrict__ scale) {
    int row  = blockIdx.x*8 + (threadIdx.x >> 5);
    int lane = threadIdx.x & 31;
    const float4* rp = (const float4*)(src + (size_t)row*HID);
    float4 v0 = rp[lane*2], v1 = rp[lane*2 + 1];
    float am = fmaxf(fmaxf(fmaxf(fabsf(v0.x), fabsf(v0.y)), fmaxf(fabsf(v0.z), fabsf(v0.w))),
                     fmaxf(fmaxf(fabsf(v1.x), fabsf(v1.y)), fmaxf(fabsf(v1.z), fabsf(v1.w))));
#pragma unroll
    for (int o = 16; o > 0; o >>= 1) am = fmaxf(am, __shfl_xor_sync(0xffffffffu, am, o));
    float inv = (am > 0.f) ? 16256.f/am : 0.f;
    if (lane == 0) scale[row] = (am > 0.f) ? am/16256.f : 0.f;
    uint32_t* hp = (uint32_t*)hi;
    uint32_t* lp = (uint32_t*)lo;
#pragma unroll
    for (int j = 0; j < 2; j++) {
        float4 v = j ? v1 : v0;
        int h0,l0,h1,l1,h2,l2,h3,l3;
        q2(v.x, inv, h0, l0); q2(v.y, inv, h1, l1);
        q2(v.z, inv, h2, l2); q2(v.w, inv, h3, l3);
        uint32_t hw = (uint32_t)(h0 & 255) | ((uint32_t)(h1 & 255) << 8)
                    | ((uint32_t)(h2 & 255) << 16) | ((uint32_t)(h3 & 255) << 24);
        uint32_t lw = (uint32_t)(l0 & 255) | ((uint32_t)(l1 & 255) << 8)
                    | ((uint32_t)(l2 & 255) << 16) | ((uint32_t)(l3 & 255) << 24);
        size_t idx = (size_t)row*64 + lane*2 + j;
        hp[idx] = hw;
        lp[idx] = lw;
    }
}
// quantize+transpose weight W [K,256] -> planes [256 out][K] + out scale. warp/out-row.
__global__ __launch_bounds__(256, 4)
void quant_wt_kernel(const float* __restrict__ W,
                     unsigned char* __restrict__ WH, unsigned char* __restrict__ WL,
                     float* __restrict__ sc, int K) {
    int n    = blockIdx.x*8 + (threadIdx.x >> 5);
    int lane = threadIdx.x & 31;
    float am = 0.f;
    for (int k = lane; k < K; k += 32)
        am = fmaxf(am, fabsf(W[(size_t)k*256 + n]));
#pragma unroll
    for (int o = 16; o > 0; o >>= 1) am = fmaxf(am, __shfl_xor_sync(0xffffffffu, am, o));
    float inv = (am > 0.f) ? 16256.f/am : 0.f;
    if (lane == 0) sc[n] = (am > 0.f) ? am/16256.f : 0.f;
    for (int k = lane; k < K; k += 32) {
        int h, l;
        q2(W[(size_t)k*256 + n], inv, h, l);
        WH[(size_t)n*K + k] = (unsigned char)(h & 255);
        WL[(size_t)n*K + k] = (unsigned char)(l & 255);
    }
}
// edge scatter: S[dst] += relu(P[dst] + Q[src])
__global__ __launch_bounds__(256, 8)
void edge_scatter_kernel(const int* __restrict__ srcI, const int* __restrict__ dstI) {
    int e    = blockIdx.x*8 + (threadIdx.x >> 5);
    int lane = threadIdx.x & 31;
    int s = __ldg(srcI + e), d = __ldg(dstI + e);
    const float4* Pp = (const float4*)(d_P + (size_t)d*HID);
    const float4* Qp = (const float4*)(d_Q + (size_t)s*HID);
    float* Sp = d_agg + (size_t)d*HID;
#pragma unroll
    for (int j = 0; j < 2; j++) {
        int idx = lane + j*32;
        float4 p = Pp[idx], q = Qp[idx];
        red_add_v4(Sp + idx*4,
                   fmaxf(p.x + q.x, 0.f), fmaxf(p.y + q.y, 0.f),
                   fmaxf(p.z + q.z, 0.f), fmaxf(p.w + q.w, 0.f));
    }
}

// ---------------- int8 2-slice IMMA GEMM: [M,256] @ [256,256] ----------------
// CTA tile 128M x 128N (grid.y = N half), BK=32, 256 thr, 8 warps (2M x 4N(32)).
// A,B int8 hi/lo planes with row/out scales. val = sA*sB*(hh*16384 + x*128).
// Smem/stage: Ah 6144 | Al 6144 | Bh 6144 | Bl 6144 = 24576 (row stride 48B).
// DUAL: blockIdx.x split -> (bias,out,koffB=+256) pair (msg W1 top/bot).
// EPI: 2 = BN+relu+residual -> d_h   3 = raw -> out   4 = +bias -> out
//      6 = relu(Ain2 + acc + bias + b2f*cvec) -> out
#define APL 6144
#define STG 24576
#define SMEM_I (2*STG)

template<int DUAL, int EPI>
__global__ __launch_bounds__(256, 1)
void ig(const unsigned char* __restrict__ BH, const unsigned char* __restrict__ BL,
        const float* __restrict__ sB, int ldB,
        const float* __restrict__ bias,  float* __restrict__ outp,
        const float* __restrict__ biasB, float* __restrict__ outpB,
        const unsigned char* __restrict__ AH, const unsigned char* __restrict__ AL,
        const float* __restrict__ sA,
        const float* __restrict__ Ain2, const float* __restrict__ cvec, int layer)
{
    extern __shared__ char dynsmem[];
    const uint32_t smem_base = smem_u32(dynsmem);

    const int tid  = threadIdx.x;
    const int lane = tid & 31;
    const int wid  = tid >> 5;
    const int wm   = wid & 1;
    const int wn   = wid >> 1;
    const int g    = lane >> 2;
    const int t4   = lane & 3;

    int bx = blockIdx.x, sel = 0;
    if constexpr (DUAL) {
        const int halfGrid = gridDim.x >> 1;
        sel = bx >= halfGrid;
        bx -= sel * halfGrid;
    }
    const int row0 = bx * 128;
    const int nyo  = blockIdx.y * 128;
    const int koffB = DUAL ? sel*256 : 0;

    // loader: thread -> (row r = tid>>1, 16B half)
    const int r_ld = tid >> 1;
    const int hh_ld = (tid & 1) * 16;
    const uint32_t sOff = (uint32_t)r_ld*48u + (uint32_t)hh_ld;
    const size_t gA = (size_t)(row0 + r_ld)*HID + hh_ld;
    const size_t gB = (size_t)(nyo + r_ld)*ldB + hh_ld + koffB;

    int acc1[4][4][4], acc2[4][4][4];
#pragma unroll
    for (int mi = 0; mi < 4; mi++)
#pragma unroll
        for (int ni = 0; ni < 4; ni++)
#pragma unroll
            for (int r = 0; r < 4; r++) { acc1[mi][ni][r] = 0; acc2[mi][ni][r] = 0; }

    auto load_chunk = [&](int t, int stage) {
        const int k0 = t*32;
        const uint32_t sa = smem_base + (uint32_t)stage*STG;
        cp_async16(sa + sOff,          AH + gA + k0);
        cp_async16(sa + APL + sOff,    AL + gA + k0);
        cp_async16(sa + 2*APL + sOff,  BH + gB + k0);
        cp_async16(sa + 3*APL + sOff,  BL + gB + k0);
    };

    load_chunk(0, 0);
    CP_COMMIT();

    for (int t = 0; t < 8; t++) {
        if (t < 7) { load_chunk(t + 1, (t + 1) & 1); CP_COMMIT(); CP_WAIT1(); }
        else       { CP_WAIT0(); }
        __syncthreads();

        const char* stg = dynsmem + (t & 1)*STG;
        uint32_t ah[4][4], al[4][4];
#pragma unroll
        for (int mi = 0; mi < 4; mi++) {
            const uint32_t ro = (uint32_t)(wm*64 + mi*16 + g)*48u + t4*4u;
            ah[mi][0] = *(const uint32_t*)(stg + ro);
            ah[mi][1] = *(const uint32_t*)(stg + ro + 8*48);
            ah[mi][2] = *(const uint32_t*)(stg + ro + 16);
            ah[mi][3] = *(const uint32_t*)(stg + ro + 8*48 + 16);
            al[mi][0] = *(const uint32_t*)(stg + APL + ro);
            al[mi][1] = *(const uint32_t*)(stg + APL + ro + 8*48);
            al[mi][2] = *(const uint32_t*)(stg + APL + ro + 16);
            al[mi][3] = *(const uint32_t*)(stg + APL + ro + 8*48 + 16);
        }
        uint32_t bh[4][2], bl[4][2];
#pragma unroll
        for (int ni = 0; ni < 4; ni++) {
            const uint32_t no = (uint32_t)(wn*32 + ni*8 + g)*48u + t4*4u;
            bh[ni][0] = *(const uint32_t*)(stg + 2*APL + no);
            bh[ni][1] = *(const uint32_t*)(stg + 2*APL + no + 16);
            bl[ni][0] = *(const uint32_t*)(stg + 3*APL + no);
            bl[ni][1] = *(const uint32_t*)(stg + 3*APL + no + 16);
        }
#pragma unroll
        for (int ni = 0; ni < 4; ni++)
#pragma unroll
            for (int mi = 0; mi < 4; mi++) {
                mma_s8(acc1[mi][ni], ah[mi], bh[ni]);
                mma_s8(acc2[mi][ni], ah[mi], bl[ni]);
                mma_s8(acc2[mi][ni], al[mi], bh[ni]);
            }
        __syncthreads();
    }

    // ---- epilogue ----
    const float* biasSel = bias;
    float*       outSel  = outp;
    if constexpr (DUAL) {
        biasSel = sel ? biasB : bias;
        outSel  = sel ? outpB : outp;
    }
    const int colb = nyo + wn*32 + t4*2;     // + ni*8
    float2 sb2[4], bias2[4], sc2[4], sh2[4], cv2[4];
#pragma unroll
    for (int ni = 0; ni < 4; ni++) {
        sb2[ni] = *(const float2*)(sB + colb + ni*8);
        if constexpr (EPI != 3) bias2[ni] = *(const float2*)(biasSel + colb + ni*8);
        if constexpr (EPI == 2) {
            sc2[ni] = *(const float2*)(d_bnscale + layer*HID + colb + ni*8);
            sh2[ni] = *(const float2*)(d_bnshift + layer*HID + colb + ni*8);
        }
        if constexpr (EPI == 6) cv2[ni] = *(const float2*)(cvec + colb + ni*8);
    }

#pragma unroll
    for (int mi = 0; mi < 4; mi++) {
#pragma unroll
        for (int rh = 0; rh < 2; rh++) {
            const int row = row0 + wm*64 + mi*16 + g + rh*8;
            const float sar = __ldg(sA + row);
#pragma unroll
            for (int ni = 0; ni < 4; ni++) {
                float v0 = sar * sb2[ni].x *
                    ((float)acc1[mi][ni][rh*2+0]*16384.f + (float)acc2[mi][ni][rh*2+0]*128.f);
                float v1 = sar * sb2[ni].y *
                    ((float)acc1[mi][ni][rh*2+1]*16384.f + (float)acc2[mi][ni][rh*2+1]*128.f);
                if constexpr (EPI == 3) {
                    *(float2*)(outSel + (size_t)row*HID + colb + ni*8) = make_float2(v0, v1);
                } else if constexpr (EPI == 4) {
                    *(float2*)(outSel + (size_t)row*HID + colb + ni*8) =
                        make_float2(v0 + bias2[ni].x, v1 + bias2[ni].y);
                } else if constexpr (EPI == 6) {
                    const float bf = __ldg(d_b2f + row);
                    const float* tp = Ain2 + (size_t)row*HID + colb + ni*8;
                    float2 tv = *(const float2*)tp;
                    float u0 = tv.x + v0 + bias2[ni].x + bf*cv2[ni].x;
                    float u1 = tv.y + v1 + bias2[ni].y + bf*cv2[ni].y;
                    *(float2*)(outSel + (size_t)row*HID + colb + ni*8) =
                        make_float2(fmaxf(u0, 0.f), fmaxf(u1, 0.f));
                } else { // EPI == 2
                    float* hp = d_h + (size_t)row*HID + colb + ni*8;
                    float2 res = *(float2*)hp;
                    float u0 = fmaf(v0 + bias2[ni].x, sc2[ni].x, sh2[ni].x);
                    float u1 = fmaf(v1 + bias2[ni].y, sc2[ni].y, sh2[ni].y);
                    *(float2*)hp = make_float2(fmaxf(u0,0.f) + res.x, fmaxf(u1,0.f) + res.y);
                }
            }
        }
    }
}

// out[row] = relu(R[u]+S[v]) . w2 + b2
__global__ void final_pair_dot_kernel(const float* __restrict__ w2,
                                      const float* __restrict__ b2,
                                      float* __restrict__ out) {
    int row  = blockIdx.x*8 + (threadIdx.x >> 5);
    int lane = threadIdx.x & 31;
    int gg = row / 80, bb = row % 80;
    const float* R = d_P + (size_t)(gg*NPG + (bb % 57))*HID;
    const float* S = d_Q + (size_t)(gg*NPG + ((bb*13 + 1) % 57))*HID;
    float s = 0.f;
#pragma unroll
    for (int k = lane; k < HID; k += 32) {
        float v = fmaxf(R[k] + S[k], 0.f);
        s = fmaf(v, __ldg(w2 + k), s);
    }
#pragma unroll
    for (int o = 16; o > 0; o >>= 1) s += __shfl_down_sync(0xffffffffu, s, o);
    if (lane == 0) out[row] = s + b2[0];
}

// ---------------- launch ----------------
extern "C" void kernel_launch(void* const* d_in, const int* in_sizes, int n_in,
                              void* d_out, int out_size)
{
    const float* x      = (const float*)d_in[0];
    const int*   ei     = (const int*)  d_in[1];
    const float* in_w   = (const float*)d_in[3];
    const float* in_b   = (const float*)d_in[4];
    const float* msg_w1 = (const float*)d_in[5];
    const float* msg_b1 = (const float*)d_in[6];
    const float* msg_w2 = (const float*)d_in[7];
    const float* msg_b2 = (const float*)d_in[8];
    const float* upd_w1 = (const float*)d_in[9];
    const float* upd_b1 = (const float*)d_in[10];
    const float* upd_w2 = (const float*)d_in[11];
    const float* upd_b2 = (const float*)d_in[12];
    const float* bn_g   = (const float*)d_in[13];
    const float* bn_b   = (const float*)d_in[14];
    const float* bn_m   = (const float*)d_in[15];
    const float* bn_v   = (const float*)d_in[16];
    const float* mlp_w1 = (const float*)d_in[17];
    const float* mlp_b1 = (const float*)d_in[18];
    const float* mlp_w2 = (const float*)d_in[19];
    const float* mlp_b2 = (const float*)d_in[20];
    float* out = (float*)d_out;

    const int* srcI = ei;
    const int* dstI = ei + NEDGES;

    cudaFuncSetAttribute(ig<1,4>, cudaFuncAttributeMaxDynamicSharedMemorySize, SMEM_I);
    cudaFuncSetAttribute(ig<0,3>, cudaFuncAttributeMaxDynamicSharedMemorySize, SMEM_I);
    cudaFuncSetAttribute(ig<0,6>, cudaFuncAttributeMaxDynamicSharedMemorySize, SMEM_I);
    cudaFuncSetAttribute(ig<0,2>, cudaFuncAttributeMaxDynamicSharedMemorySize, SMEM_I);

    float *pP, *pQ, *pT2, *pAgg, *pWcf, *pCv, *pH, *pZero;
    cudaGetSymbolAddress((void**)&pP,    d_P);
    cudaGetSymbolAddress((void**)&pQ,    d_Q);
    cudaGetSymbolAddress((void**)&pT2,   d_t2);
    cudaGetSymbolAddress((void**)&pAgg,  d_agg);
    cudaGetSymbolAddress((void**)&pWcf,  d_wcf);
    cudaGetSymbolAddress((void**)&pCv,   d_cvec);
    cudaGetSymbolAddress((void**)&pH,    d_h);
    cudaGetSymbolAddress((void**)&pZero, d_zeros);
    unsigned char *pH8h,*pH8l,*pA8h,*pA8l,*pT8h,*pT8l;
    cudaGetSymbolAddress((void**)&pH8h, d_h8h); cudaGetSymbolAddress((void**)&pH8l, d_h8l);
    cudaGetSymbolAddress((void**)&pA8h, d_a8h); cudaGetSymbolAddress((void**)&pA8l, d_a8l);
    cudaGetSymbolAddress((void**)&pT8h, d_t8h); cudaGetSymbolAddress((void**)&pT8l, d_t8l);
    float *pSh,*pSa,*pSt;
    cudaGetSymbolAddress((void**)&pSh, d_sh);
    cudaGetSymbolAddress((void**)&pSa, d_sa);
    cudaGetSymbolAddress((void**)&pSt, d_st);
    unsigned char *pWm1h,*pWm1l,*pWu1h,*pWu1l,*pWu2h,*pWu2l,*pWch,*pWcl,*pWrh,*pWrl;
    cudaGetSymbolAddress((void**)&pWm1h, d_w8h_m1); cudaGetSymbolAddress((void**)&pWm1l, d_w8l_m1);
    cudaGetSymbolAddress((void**)&pWu1h, d_w8h_u1); cudaGetSymbolAddress((void**)&pWu1l, d_w8l_u1);
    cudaGetSymbolAddress((void**)&pWu2h, d_w8h_u2); cudaGetSymbolAddress((void**)&pWu2l, d_w8l_u2);
    cudaGetSymbolAddress((void**)&pWch,  d_w8h_c ); cudaGetSymbolAddress((void**)&pWcl,  d_w8l_c );
    cudaGetSymbolAddress((void**)&pWrh,  d_w8h_r ); cudaGetSymbolAddress((void**)&pWrl,  d_w8l_r );
    float *pSm1,*pSu1,*pSu2,*pSc,*pSr;
    cudaGetSymbolAddress((void**)&pSm1, d_ws_m1);
    cudaGetSymbolAddress((void**)&pSu1, d_ws_u1);
    cudaGetSymbolAddress((void**)&pSu2, d_ws_u2);
    cudaGetSymbolAddress((void**)&pSc,  d_ws_c);
    cudaGetSymbolAddress((void**)&pSr,  d_ws_r);

    // prep
    deg_zero_kernel <<<(NNODES+255)/256, 256>>>();
    deg_count_kernel<<<(NEDGES+255)/256, 256>>>(dstI);
    deg_inv_kernel  <<<(NNODES+255)/256, 256>>>();
    bn_prep_kernel  <<<(NLAY*HID+255)/256, 256>>>(bn_g, bn_b, bn_m, bn_v);
    input_gemm_kernel<<<NNODES, 256>>>(x, in_w, in_b);
    quant_rows_kernel<<<NNODES/8, 256>>>(pH, pH8h, pH8l, pSh);

    // weight quantization
    for (int l = 0; l < NLAY; l++) {
        quant_wt_kernel<<<32, 256>>>(msg_w1 + (size_t)l*512*HID,
            pWm1h + (size_t)l*256*512, pWm1l + (size_t)l*256*512, pSm1 + l*256, 512);
        quant_wt_kernel<<<32, 256>>>(upd_w1 + (size_t)l*512*HID,
            pWu1h + (size_t)l*256*512, pWu1l + (size_t)l*256*512, pSu1 + l*256, 512);
        quant_wt_kernel<<<32, 256>>>(upd_w2 + (size_t)l*HID*HID,
            pWu2h + (size_t)l*256*256, pWu2l + (size_t)l*256*256, pSu2 + l*256, 256);
        cgemm_kernel<<<256, 256>>>(msg_w2 + (size_t)l*HID*HID, upd_w1 + (size_t)l*512*HID);
        quant_wt_kernel<<<32, 256>>>(pWcf,
            pWch + (size_t)l*256*256, pWcl + (size_t)l*256*256, pSc + l*256, 256);
        cvec_kernel<<<1, 256>>>(msg_b2 + l*HID, upd_w1 + (size_t)l*512*HID, pCv + l*HID);
    }
    quant_wt_kernel<<<32, 256>>>(mlp_w1, pWrh, pWrl, pSr, 512);

    dim3 gDual(2*NGRID, 2), gOne(NGRID, 2);

    for (int l = 0; l < NLAY; l++) {
        const size_t o1 = (size_t)l*256*512;
        const size_t o2 = (size_t)l*256*256;
        zero_agg_kernel<<<2048, 256>>>();
        // P = h@W1top + b1 | Q = h@W1bot
        ig<1,4><<<gDual, 256, SMEM_I>>>(pWm1h + o1, pWm1l + o1, pSm1 + l*256, 512,
            msg_b1 + l*HID, pP, pZero, pQ,
            pH8h, pH8l, pSh, nullptr, nullptr, l);
        edge_scatter_kernel<<<NEDGES/8, 256>>>(srcI, dstI);
        scale_agg_kernel<<<2048, 256>>>();
        quant_rows_kernel<<<NNODES/8, 256>>>(pAgg, pA8h, pA8l, pSa);
        // t2raw = h @ U1top
        ig<0,3><<<gOne, 256, SMEM_I>>>(pWu1h + o1, pWu1l + o1, pSu1 + l*256, 512,
            nullptr, pT2, nullptr, nullptr,
            pH8h, pH8l, pSh, nullptr, nullptr, l);
        // t2 = relu(t2raw + S@C + b1u + b2f*cvec)
        ig<0,6><<<gOne, 256, SMEM_I>>>(pWch + o2, pWcl + o2, pSc + l*256, 256,
            upd_b1 + l*HID, pT2, nullptr, nullptr,
            pA8h, pA8l, pSa, pT2, pCv + l*HID, l);
        quant_rows_kernel<<<NNODES/8, 256>>>(pT2, pT8h, pT8l, pSt);
        // h = relu(BN(t2 @ U2 + b2u)) + h
        ig<0,2><<<gOne, 256, SMEM_I>>>(pWu2h + o2, pWu2l + o2, pSu2 + l*256, 256,
            upd_b2 + l*HID, nullptr, nullptr, nullptr,
            pT8h, pT8l, pSt, nullptr, nullptr, l);
        quant_rows_kernel<<<NNODES/8, 256>>>(pH, pH8h, pH8l, pSh);
    }

    // readout: R = h@mlpW1top + b1 -> P | S = h@mlpW1bot -> Q
    ig<1,4><<<gDual, 256, SMEM_I>>>(pWrh, pWrl, pSr, 512,
        mlp_b1, pP, pZero, pQ,
        pH8h, pH8l, pSh, nullptr, nullptr, 0);
    final_pair_dot_kernel<<<NEF/8, 256>>>(mlp_w2, mlp_b2, out);
}

// round 16
// speedup vs baseline: 2.4999x; 2.4999x over previous
#include <cuda_runtime.h>
#include <cuda_bf16.h>
#include <cstdint>

#define GNUM   2048
#define NPG    57
#define NNODES (GNUM*NPG)      // 116736
#define EPG    160
#define NEDGES (GNUM*EPG)      // 327680
#define HID    256
#define NLAY   5
#define NEF    (GNUM*80)       // 163840
#define NBLK   114             // NNODES/1024

// ---------------- scratch (static __device__ arrays; no allocs) ----------------
__device__ float d_h   [(size_t)NNODES*HID];
__device__ float d_t2  [(size_t)NNODES*HID];
__device__ float d_agg [(size_t)NNODES*HID];   // S (written whole by gather)
__device__ float d_P   [(size_t)NNODES*HID];
__device__ float d_Q   [(size_t)NNODES*HID];
__device__ float d_invdeg [NNODES];
__device__ float d_b2f    [NNODES];
__device__ float d_bnscale[NLAY*HID];
__device__ float d_bnshift[NLAY*HID];
__device__ float d_wcf [(size_t)256*256];
__device__ float d_cvec[(size_t)NLAY*HID];
__device__ float d_zeros[HID];                 // stays zero (.bss)
// CSR edge grouping (built once per launch)
__device__ int d_deg [NNODES];
__device__ int d_off [NNODES];
__device__ int d_fill[NNODES];
__device__ int d_blksum[NBLK];
__device__ int d_srcSorted[NEDGES];
// transposed, bf16-split weights: [256 out, K] K-major, hi + lo
__device__ unsigned short d_bhi_m1[(size_t)NLAY*256*512];
__device__ unsigned short d_blo_m1[(size_t)NLAY*256*512];
__device__ unsigned short d_bhi_u1[(size_t)NLAY*256*512];
__device__ unsigned short d_blo_u1[(size_t)NLAY*256*512];
__device__ unsigned short d_bhi_u2[(size_t)NLAY*256*256];
__device__ unsigned short d_blo_u2[(size_t)NLAY*256*256];
__device__ unsigned short d_bhi_c [(size_t)NLAY*256*256];
__device__ unsigned short d_blo_c [(size_t)NLAY*256*256];
__device__ unsigned short d_bhi_r [(size_t)256*512];
__device__ unsigned short d_blo_r [(size_t)256*512];

// ---------------- PTX helpers ----------------
__device__ __forceinline__ uint32_t smem_u32(const void* p) {
    uint32_t a;
    asm("{ .reg .u64 t; cvta.to.shared.u64 t, %1; cvt.u32.u64 %0, t; }" : "=r"(a) : "l"(p));
    return a;
}
__device__ __forceinline__ void cp_async16(uint32_t smem, const void* g) {
    asm volatile("cp.async.cg.shared.global [%0], [%1], 16;" :: "r"(smem), "l"(g) : "memory");
}
#define CP_COMMIT() asm volatile("cp.async.commit_group;" ::: "memory")
#define CP_WAIT1()  asm volatile("cp.async.wait_group 1;" ::: "memory")
#define CP_WAIT0()  asm volatile("cp.async.wait_group 0;" ::: "memory")

__device__ __forceinline__ void mma_bf16(float* d, const uint32_t* a, const uint32_t* b) {
    asm volatile(
        "mma.sync.aligned.m16n8k16.row.col.f32.bf16.bf16.f32 "
        "{%0,%1,%2,%3}, {%4,%5,%6,%7}, {%8,%9}, {%0,%1,%2,%3};"
        : "+f"(d[0]), "+f"(d[1]), "+f"(d[2]), "+f"(d[3])
        : "r"(a[0]), "r"(a[1]), "r"(a[2]), "r"(a[3]), "r"(b[0]), "r"(b[1]));
}
__device__ __forceinline__ void split_bf16x2(float2 v, uint32_t& hi, uint32_t& lo) {
    asm("cvt.rn.bf16x2.f32 %0, %1, %2;" : "=r"(hi) : "f"(v.y), "f"(v.x));
    float hlo = __uint_as_float(hi << 16);
    float hhi = __uint_as_float(hi & 0xFFFF0000u);
    asm("cvt.rn.bf16x2.f32 %0, %1, %2;" : "=r"(lo) : "f"(v.y - hhi), "f"(v.x - hlo));
}

// ---------------- small helper kernels ----------------
__global__ void deg_zero_kernel() {
    int i = blockIdx.x*blockDim.x + threadIdx.x;
    if (i < NNODES) d_deg[i] = 0;
}
__global__ void deg_count_kernel(const int* __restrict__ dst) {
    int e = blockIdx.x*blockDim.x + threadIdx.x;
    if (e < NEDGES) atomicAdd(&d_deg[dst[e]], 1);
}
__global__ void deg_inv_kernel() {
    int i = blockIdx.x*blockDim.x + threadIdx.x;
    if (i < NNODES) {
        int c = d_deg[i];
        d_invdeg[i] = 1.f / fmaxf((float)c, 1.f);
        d_b2f[i] = (c > 0) ? 1.f : 0.f;
    }
}
// CSR build: block sums -> scan of block sums -> in-block exclusive scan -> fill
__global__ void ps_block_sum_kernel() {
    __shared__ int sh[1024];
    int i = blockIdx.x*1024 + threadIdx.x;
    sh[threadIdx.x] = (i < NNODES) ? d_deg[i] : 0;
    __syncthreads();
    for (int o = 512; o > 0; o >>= 1) {
        if (threadIdx.x < o) sh[threadIdx.x] += sh[threadIdx.x + o];
        __syncthreads();
    }
    if (threadIdx.x == 0) d_blksum[blockIdx.x] = sh[0];
}
__global__ void ps_scan_blocks_kernel() {
    if (threadIdx.x == 0) {
        int acc = 0;
        for (int b = 0; b < NBLK; b++) { int v = d_blksum[b]; d_blksum[b] = acc; acc += v; }
    }
}
__global__ void ps_scan_within_kernel() {
    __shared__ int sh[1024];
    int i = blockIdx.x*1024 + threadIdx.x;
    int v = (i < NNODES) ? d_deg[i] : 0;
    sh[threadIdx.x] = v;
    __syncthreads();
    for (int o = 1; o < 1024; o <<= 1) {
        int t = (threadIdx.x >= o) ? sh[threadIdx.x - o] : 0;
        __syncthreads();
        sh[threadIdx.x] += t;
        __syncthreads();
    }
    if (i < NNODES) {
        d_off[i]  = d_blksum[blockIdx.x] + sh[threadIdx.x] - v;  // exclusive
        d_fill[i] = 0;
    }
}
__global__ void fill_kernel(const int* __restrict__ src, const int* __restrict__ dst) {
    int e = blockIdx.x*256 + threadIdx.x;
    if (e < NEDGES) {
        int d = dst[e];
        int pos = atomicAdd(&d_fill[d], 1);
        d_srcSorted[d_off[d] + pos] = src[e];
    }
}
__global__ void bn_prep_kernel(const float* __restrict__ g, const float* __restrict__ b,
                               const float* __restrict__ m, const float* __restrict__ v) {
    int i = blockIdx.x*blockDim.x + threadIdx.x;
    if (i < NLAY*HID) {
        float sc = g[i] * rsqrtf(v[i] + 1e-5f);
        d_bnscale[i] = sc;
        d_bnshift[i] = b[i] - m[i]*sc;
    }
}
__global__ void input_gemm_kernel(const float* __restrict__ x,
                                  const float* __restrict__ w,
                                  const float* __restrict__ b) {
    int n = blockIdx.x;
    int c = threadIdx.x;
    __shared__ float xs[16];
    if (c < 16) xs[c] = x[n*16 + c];
    __syncthreads();
    float acc = b[c];
#pragma unroll
    for (int k = 0; k < 16; k++) acc = fmaf(xs[k], w[k*HID + c], acc);
    d_h[(size_t)n*HID + c] = acc;
}
__global__ void cvec_kernel(const float* __restrict__ b2,
                            const float* __restrict__ u1,
                            float* __restrict__ outc) {
    int n = threadIdx.x;
    float s = 0.f;
    for (int k = 0; k < 256; k++)
        s = fmaf(b2[k], u1[(size_t)(256 + k)*256 + n], s);
    outc[n] = s;
}
// W [K,256] row-major -> hi/lo bf16 [256,K] row-major
template<int DSEL>
__global__ void transpose_split_kernel(const float* __restrict__ W, int layer, int K) {
    __shared__ float tile[32][33];
    unsigned short *WH, *WL;
    if      constexpr (DSEL == 0) { WH = d_bhi_m1 + (size_t)layer*256*512; WL = d_blo_m1 + (size_t)layer*256*512; }
    else if constexpr (DSEL == 2) { WH = d_bhi_u1 + (size_t)layer*256*512; WL = d_blo_u1 + (size_t)layer*256*512; }
    else if constexpr (DSEL == 3) { WH = d_bhi_u2 + (size_t)layer*256*256; WL = d_blo_u2 + (size_t)layer*256*256; }
    else if constexpr (DSEL == 5) { WH = d_bhi_c  + (size_t)layer*256*256; WL = d_blo_c  + (size_t)layer*256*256; }
    else                          { WH = d_bhi_r; WL = d_blo_r; }
    int kb = blockIdx.x*32, nb = blockIdx.y*32;
    for (int r = threadIdx.y; r < 32; r += 8)
        tile[r][threadIdx.x] = W[(size_t)(kb + r)*256 + nb + threadIdx.x];
    __syncthreads();
    for (int r = threadIdx.y; r < 32; r += 8) {
        float v = tile[threadIdx.x][r];
        __nv_bfloat16 hb = __float2bfloat16(v);
        __nv_bfloat16 lb = __float2bfloat16(v - __bfloat162float(hb));
        size_t o = (size_t)(nb + r)*K + kb + threadIdx.x;
        WH[o] = __bfloat16_as_ushort(hb);
        WL[o] = __bfloat16_as_ushort(lb);
    }
}

// gather: warp per node.  S[n] = invdeg[n] * sum_{e in CSR[n]} relu(P[n] + Q[src_e])
__global__ __launch_bounds__(256, 8)
void gather_kernel() {
    int n    = blockIdx.x*8 + (threadIdx.x >> 5);
    int lane = threadIdx.x & 31;
    const float4* Pp = (const float4*)(d_P + (size_t)n*HID);
    float4 p0 = Pp[lane], p1 = Pp[lane + 32];
    float4 a0 = make_float4(0.f,0.f,0.f,0.f), a1 = a0;
    const int beg = d_off[n];
    const int end = beg + d_deg[n];
    for (int e = beg; e < end; e++) {
        int s = __ldg(d_srcSorted + e);
        const float4* Qp = (const float4*)(d_Q + (size_t)s*HID);
        float4 q0 = Qp[lane], q1 = Qp[lane + 32];
        a0.x += fmaxf(p0.x + q0.x, 0.f); a0.y += fmaxf(p0.y + q0.y, 0.f);
        a0.z += fmaxf(p0.z + q0.z, 0.f); a0.w += fmaxf(p0.w + q0.w, 0.f);
        a1.x += fmaxf(p1.x + q1.x, 0.f); a1.y += fmaxf(p1.y + q1.y, 0.f);
        a1.z += fmaxf(p1.z + q1.z, 0.f); a1.w += fmaxf(p1.w + q1.w, 0.f);
    }
    float iv = d_invdeg[n];
    a0.x*=iv; a0.y*=iv; a0.z*=iv; a0.w*=iv;
    a1.x*=iv; a1.y*=iv; a1.z*=iv; a1.w*=iv;
    float4* Sp = (float4*)(d_agg + (size_t)n*HID);
    Sp[lane] = a0; Sp[lane + 32] = a1;
}

// ---------------- bf16x3 split mma.sync GEMM (R10 engine, unchanged) ----------
#define AROWSTR  40
#define BROWSTR  40
#define A_BYTES  (128*AROWSTR*4)
#define BH_BYTES (256*BROWSTR*2)
#define STG_F    (A_BYTES + 2*BH_BYTES)
#define SMEM_F   (2*STG_F)

template<int CONCAT, int DUAL, int EPI>
__global__ __launch_bounds__(256, 1)
void tc_gemm(const unsigned short* __restrict__ WH1, const unsigned short* __restrict__ WL1,
             int ldB1,
             const unsigned short* __restrict__ WH2, const unsigned short* __restrict__ WL2,
             int ldB2,
             const float* __restrict__ bias,  float* __restrict__ outp,
             const float* __restrict__ biasB, float* __restrict__ outpB,
             const float* __restrict__ Ain,  const float* __restrict__ Ain2,
             const float* __restrict__ cvec,
             int K, int layer)
{
    extern __shared__ char dynsmem[];
    const uint32_t smem_base = smem_u32(dynsmem);

    const int tid  = threadIdx.x;
    const int lane = tid & 31;
    const int wid  = tid >> 5;
    const int wm   = wid & 1;
    const int wn   = wid >> 1;
    const int g    = lane >> 2;
    const int t4   = lane & 3;

    int bx = blockIdx.x, sel = 0;
    if constexpr (DUAL) {
        const int halfGrid = gridDim.x >> 1;
        sel = bx >= halfGrid;
        bx -= sel * halfGrid;
    }
    const int row0 = bx * 128;
    const int koffB = DUAL ? sel*256 : 0;

    const int rt = tid >> 3;
    const int cc = tid & 7;
    uint32_t sAoff[4], sBoff[8];
#pragma unroll
    for (int j = 0; j < 4; j++)
        sAoff[j] = (uint32_t)(rt + j*32)*(AROWSTR*4u) + (uint32_t)cc*16u;
#pragma unroll
    for (int j = 0; j < 8; j++)
        sBoff[j] = (uint32_t)(rt + j*32)*(BROWSTR*2u) + (uint32_t)(cc & 3)*16u;

    uint32_t aofs[4];
#pragma unroll
    for (int j = 0; j < 4; j++)
        aofs[j] = (uint32_t)(row0 + rt + j*32)*HID + cc*4u;

    const unsigned short* gB1 = ((cc < 4) ? WH1 : WL1) + (size_t)rt*ldB1 + (cc & 3)*8 + koffB;
    const unsigned short* gB2 = nullptr;
    if constexpr (CONCAT)
        gB2 = ((cc < 4) ? WH2 : WL2) + (size_t)rt*ldB2 + (cc & 3)*8;
    const uint32_t sBsel = (cc < 4) ? 0u : BH_BYTES;

    float acc[4][8][4];
#pragma unroll
    for (int mi = 0; mi < 4; mi++)
#pragma unroll
        for (int ni = 0; ni < 8; ni++)
#pragma unroll
            for (int r = 0; r < 4; r++) acc[mi][ni][r] = 0.f;

    const int NC = K >> 5;

    auto load_chunk = [&](int t, int stage) {
        const int k0 = t*32;
        uint32_t sa  = smem_base + (uint32_t)stage*STG_F;
        uint32_t sbh = sa + A_BYTES + sBsel;
        if (CONCAT && k0 >= 256) {
            const int kin = k0 - 256;
#pragma unroll
            for (int j = 0; j < 4; j++)
                cp_async16(sa + sAoff[j], Ain2 + aofs[j] + kin);
#pragma unroll
            for (int j = 0; j < 8; j++)
                cp_async16(sbh + sBoff[j], gB2 + (size_t)j*32*ldB2 + kin);
        } else {
#pragma unroll
            for (int j = 0; j < 4; j++)
                cp_async16(sa + sAoff[j], Ain + aofs[j] + k0);
#pragma unroll
            for (int j = 0; j < 8; j++)
                cp_async16(sbh + sBoff[j], gB1 + (size_t)j*32*ldB1 + k0);
        }
    };

    load_chunk(0, 0);
    CP_COMMIT();

    for (int t = 0; t < NC; t++) {
        if (t + 1 < NC) { load_chunk(t + 1, (t + 1) & 1); CP_COMMIT(); CP_WAIT1(); }
        else            { CP_WAIT0(); }
        __syncthreads();

        const char*  stg = dynsmem + (t & 1)*STG_F;
        const float* sA  = (const float*)stg;
        const char*  sBH = stg + A_BYTES;
        const char*  sBL = sBH + BH_BYTES;
#pragma unroll
        for (int ks = 0; ks < 2; ks++) {
            const int kf = ks*16 + t4*2;
            uint32_t ahi[4][4], alo[4][4];
#pragma unroll
            for (int mi = 0; mi < 4; mi++) {
                const float* ap = sA + (wm*64 + mi*16 + g)*AROWSTR + kf;
                float2 v00 = *(const float2*)ap;
                float2 v10 = *(const float2*)(ap + 8*AROWSTR);
                float2 v01 = *(const float2*)(ap + 8);
                float2 v11 = *(const float2*)(ap + 8*AROWSTR + 8);
                split_bf16x2(v00, ahi[mi][0], alo[mi][0]);
                split_bf16x2(v10, ahi[mi][1], alo[mi][1]);
                split_bf16x2(v01, ahi[mi][2], alo[mi][2]);
                split_bf16x2(v11, ahi[mi][3], alo[mi][3]);
            }
#pragma unroll
            for (int ni = 0; ni < 8; ni++) {
                const uint32_t boff = (uint32_t)(wn*64 + ni*8 + g)*(BROWSTR*2u)
                                    + (uint32_t)(ks*16 + t4*2)*2u;
                uint32_t bhi[2] = { *(const uint32_t*)(sBH + boff),
                                    *(const uint32_t*)(sBH + boff + 16) };
                uint32_t blo[2] = { *(const uint32_t*)(sBL + boff),
                                    *(const uint32_t*)(sBL + boff + 16) };
#pragma unroll
                for (int mi = 0; mi < 4; mi++) {
                    mma_bf16(acc[mi][ni], ahi[mi], bhi);
                    mma_bf16(acc[mi][ni], ahi[mi], blo);
                    mma_bf16(acc[mi][ni], alo[mi], bhi);
                }
            }
        }
        __syncthreads();
    }

    // ---- epilogue ----
    const float* biasSel = bias;
    float*       outSel  = outp;
    if constexpr (DUAL) {
        biasSel = sel ? biasB : bias;
        outSel  = sel ? outpB : outp;
    }
    const int colb = wn*64 + t4*2;
    float2 bias2[8];
    if constexpr (EPI != 3) {
#pragma unroll
        for (int ni = 0; ni < 8; ni++)
            bias2[ni] = *(const float2*)(biasSel + colb + ni*8);
    }
    float2 sc2[8], sh2[8];
    if constexpr (EPI == 2) {
#pragma unroll
        for (int ni = 0; ni < 8; ni++) {
            sc2[ni] = *(const float2*)(d_bnscale + layer*HID + colb + ni*8);
            sh2[ni] = *(const float2*)(d_bnshift + layer*HID + colb + ni*8);
        }
    }
    float2 cv2[8];
    if constexpr (EPI == 7) {
#pragma unroll
        for (int ni = 0; ni < 8; ni++)
            cv2[ni] = *(const float2*)(cvec + colb + ni*8);
    }

#pragma unroll
    for (int mi = 0; mi < 4; mi++) {
#pragma unroll
        for (int rh = 0; rh < 2; rh++) {
            const int row = row0 + wm*64 + mi*16 + g + rh*8;
            if constexpr (EPI == 3) {
                float* op = outSel + (size_t)row*HID + colb;
#pragma unroll
                for (int ni = 0; ni < 8; ni++)
                    *(float2*)(op + ni*8) = make_float2(acc[mi][ni][rh*2+0],
                                                        acc[mi][ni][rh*2+1]);
            } else if constexpr (EPI == 4) {
                float* op = outSel + (size_t)row*HID + colb;
#pragma unroll
                for (int ni = 0; ni < 8; ni++)
                    *(float2*)(op + ni*8) = make_float2(acc[mi][ni][rh*2+0] + bias2[ni].x,
                                                        acc[mi][ni][rh*2+1] + bias2[ni].y);
            } else if constexpr (EPI == 7) {
                const float bf = __ldg(d_b2f + row);
                float* op = outSel + (size_t)row*HID + colb;
#pragma unroll
                for (int ni = 0; ni < 8; ni++) {
                    float u0 = acc[mi][ni][rh*2+0] + bias2[ni].x + bf*cv2[ni].x;
                    float u1 = acc[mi][ni][rh*2+1] + bias2[ni].y + bf*cv2[ni].y;
                    *(float2*)(op + ni*8) = make_float2(fmaxf(u0, 0.f), fmaxf(u1, 0.f));
                }
            } else { // EPI == 2
                float* hp = d_h + (size_t)row*HID + colb;
#pragma unroll
                for (int ni = 0; ni < 8; ni++) {
                    float2 res = *(float2*)(hp + ni*8);
                    float u0 = fmaf(acc[mi][ni][rh*2+0] + bias2[ni].x, sc2[ni].x, sh2[ni].x);
                    float u1 = fmaf(acc[mi][ni][rh*2+1] + bias2[ni].y, sc2[ni].y, sh2[ni].y);
                    *(float2*)(hp + ni*8) = make_float2(fmaxf(u0,0.f) + res.x,
                                                        fmaxf(u1,0.f) + res.y);
                }
            }
        }
    }
}

// out[row] = relu(R[u]+S[v]) . w2 + b2   (R has mlp_b1 folded in)
__global__ void final_pair_dot_kernel(const float* __restrict__ w2,
                                      const float* __restrict__ b2,
                                      float* __restrict__ out) {
    int row  = blockIdx.x*8 + (threadIdx.x >> 5);
    int lane = threadIdx.x & 31;
    int gg = row / 80, bb = row % 80;
    const float* R = d_P + (size_t)(gg*NPG + (bb % 57))*HID;
    const float* S = d_Q + (size_t)(gg*NPG + ((bb*13 + 1) % 57))*HID;
    float s = 0.f;
#pragma unroll
    for (int k = lane; k < HID; k += 32) {
        float v = fmaxf(R[k] + S[k], 0.f);
        s = fmaf(v, __ldg(w2 + k), s);
    }
#pragma unroll
    for (int o = 16; o > 0; o >>= 1) s += __shfl_down_sync(0xffffffffu, s, o);
    if (lane == 0) out[row] = s + b2[0];
}

// ---------------- launch ----------------
extern "C" void kernel_launch(void* const* d_in, const int* in_sizes, int n_in,
                              void* d_out, int out_size)
{
    const float* x      = (const float*)d_in[0];
    const int*   ei     = (const int*)  d_in[1];
    const float* in_w   = (const float*)d_in[3];
    const float* in_b   = (const float*)d_in[4];
    const float* msg_w1 = (const float*)d_in[5];
    const float* msg_b1 = (const float*)d_in[6];
    const float* msg_w2 = (const float*)d_in[7];
    const float* msg_b2 = (const float*)d_in[8];
    const float* upd_w1 = (const float*)d_in[9];
    const float* upd_b1 = (const float*)d_in[10];
    const float* upd_w2 = (const float*)d_in[11];
    const float* upd_b2 = (const float*)d_in[12];
    const float* bn_g   = (const float*)d_in[13];
    const float* bn_b   = (const float*)d_in[14];
    const float* bn_m   = (const float*)d_in[15];
    const float* bn_v   = (const float*)d_in[16];
    const float* mlp_w1 = (const float*)d_in[17];
    const float* mlp_b1 = (const float*)d_in[18];
    const float* mlp_w2 = (const float*)d_in[19];
    const float* mlp_b2 = (const float*)d_in[20];
    float* out = (float*)d_out;

    const int* srcI = ei;
    const int* dstI = ei + NEDGES;

    cudaFuncSetAttribute(tc_gemm<0,1,4>, cudaFuncAttributeMaxDynamicSharedMemorySize, SMEM_F);
    cudaFuncSetAttribute(tc_gemm<1,0,7>, cudaFuncAttributeMaxDynamicSharedMemorySize, SMEM_F);
    cudaFuncSetAttribute(tc_gemm<0,0,2>, cudaFuncAttributeMaxDynamicSharedMemorySize, SMEM_F);
    cudaFuncSetAttribute(tc_gemm<0,0,3>, cudaFuncAttributeMaxDynamicSharedMemorySize, SMEM_F);

    float *pP, *pQ, *pT2, *pAgg, *pWcf, *pCv, *pH, *pZero;
    cudaGetSymbolAddress((void**)&pP,    d_P);
    cudaGetSymbolAddress((void**)&pQ,    d_Q);
    cudaGetSymbolAddress((void**)&pT2,   d_t2);
    cudaGetSymbolAddress((void**)&pAgg,  d_agg);
    cudaGetSymbolAddress((void**)&pWcf,  d_wcf);
    cudaGetSymbolAddress((void**)&pCv,   d_cvec);
    cudaGetSymbolAddress((void**)&pH,    d_h);
    cudaGetSymbolAddress((void**)&pZero, d_zeros);
    unsigned short *pHm1,*pLm1,*pHu1,*pLu1,*pHu2,*pLu2,*pHc,*pLc,*pHr,*pLr;
    cudaGetSymbolAddress((void**)&pHm1, d_bhi_m1); cudaGetSymbolAddress((void**)&pLm1, d_blo_m1);
    cudaGetSymbolAddress((void**)&pHu1, d_bhi_u1); cudaGetSymbolAddress((void**)&pLu1, d_blo_u1);
    cudaGetSymbolAddress((void**)&pHu2, d_bhi_u2); cudaGetSymbolAddress((void**)&pLu2, d_blo_u2);
    cudaGetSymbolAddress((void**)&pHc,  d_bhi_c ); cudaGetSymbolAddress((void**)&pLc,  d_blo_c );
    cudaGetSymbolAddress((void**)&pHr,  d_bhi_r ); cudaGetSymbolAddress((void**)&pLr,  d_blo_r );

    // prep: degrees + CSR grouping (once per launch)
    deg_zero_kernel <<<(NNODES+255)/256, 256>>>();
    deg_count_kernel<<<(NEDGES+255)/256, 256>>>(dstI);
    deg_inv_kernel  <<<(NNODES+255)/256, 256>>>();
    ps_block_sum_kernel  <<<NBLK, 1024>>>();
    ps_scan_blocks_kernel<<<1, 32>>>();
    ps_scan_within_kernel<<<NBLK, 1024>>>();
    fill_kernel<<<(NEDGES+255)/256, 256>>>(srcI, dstI);
    bn_prep_kernel  <<<(NLAY*HID+255)/256, 256>>>(bn_g, bn_b, bn_m, bn_v);
    input_gemm_kernel<<<NNODES, 256>>>(x, in_w, in_b);

    dim3 tb(32, 8);
    for (int l = 0; l < NLAY; l++) {
        transpose_split_kernel<0><<<dim3(16, 8), tb>>>(msg_w1 + (size_t)l*512*HID, l, 512);
        transpose_split_kernel<2><<<dim3(16, 8), tb>>>(upd_w1 + (size_t)l*512*HID, l, 512);
        transpose_split_kernel<3><<<dim3(8,  8), tb>>>(upd_w2 + (size_t)l*HID*HID, l, 256);
    }
    transpose_split_kernel<4><<<dim3(16, 8), tb>>>(mlp_w1, 0, 512);

    // C_l = msg_w2 @ U1bot (fp32 staging), split; cvec_l = msg_b2 @ U1bot
    for (int l = 0; l < NLAY; l++) {
        const size_t o1 = (size_t)l*256*512;
        tc_gemm<0,0,3><<<2, 256, SMEM_F>>>(pHu1 + o1 + 256, pLu1 + o1 + 256, 512,
            nullptr, nullptr, 0,
            nullptr, pWcf, nullptr, nullptr,
            msg_w2 + (size_t)l*HID*HID, nullptr, nullptr, 256, l);
        transpose_split_kernel<5><<<dim3(8, 8), tb>>>(pWcf, l, 256);
        cvec_kernel<<<1, 256>>>(msg_b2 + l*HID, upd_w1 + (size_t)l*512*HID, pCv + l*HID);
    }

    const int NGRID = NNODES/128;   // 912

    for (int l = 0; l < NLAY; l++) {
        const size_t o1 = (size_t)l*256*512;
        const size_t o2 = (size_t)l*256*256;
        // fused: P = h@W1top + b1 (first half of grid) | Q = h@W1bot (second half)
        tc_gemm<0,1,4><<<2*NGRID, 256, SMEM_F>>>(pHm1 + o1, pLm1 + o1, 512,
            nullptr, nullptr, 0,
            msg_b1 + l*HID, pP, pZero, pQ,
            pH, nullptr, nullptr, 256, l);
        // S[n] = invdeg[n] * sum_{e in CSR[n]} relu(P[n] + Q[src])  (no atomics)
        gather_kernel<<<NNODES/8, 256>>>();
        // t2 = relu([h | S] @ [U1top ; C_l] + upd_b1 + b2f*cvec)   (K=512 concat)
        tc_gemm<1,0,7><<<NGRID, 256, SMEM_F>>>(pHu1 + o1, pLu1 + o1, 512,
            pHc + o2, pLc + o2, 256,
            upd_b1 + l*HID, pT2, nullptr, nullptr,
            pH, pAgg, pCv + l*HID, 512, l);
        // h = relu(BN(t2 @ U2 + b2u)) + h
        tc_gemm<0,0,2><<<NGRID, 256, SMEM_F>>>(pHu2 + o2, pLu2 + o2, 256,
            nullptr, nullptr, 0,
            upd_b2 + l*HID, nullptr, nullptr, nullptr,
            pT2, nullptr, nullptr, 256, l);
    }

    // readout fused: R = h@mlpW1top + b1 -> P | S = h@mlpW1bot -> Q
    tc_gemm<0,1,4><<<2*NGRID, 256, SMEM_F>>>(pHr, pLr, 512,
        nullptr, nullptr, 0,
        mlp_b1, pP, pZero, pQ,
        pH, nullptr, nullptr, 256, 0);
    final_pair_dot_kernel<<<NEF/8, 256>>>(mlp_w2, mlp_b2, out);
}